// round 11
// baseline (speedup 1.0000x reference)
#include <cuda_runtime.h>

// TransOp_expm via traceless Cayley-Hamilton, SCALAR fp32, 4 independent
// batches per thread (ILP=4). NSQ=3, ORDER=10.
// __launch_bounds__(256,3) caps regs at 84 (expected ~80, no spill).

#define NSQ 3
#define NORD 10

// Scalar traceless-CH core for one batch.
__device__ __forceinline__ void expm_core_s(
    float A0, float A1, float A2, float A3, float A4,
    float A5, float A6, float A7, float A8,
    float v0, float v1, float v2,
    float& y0, float& y1, float& y2)
{
    float c1 = A0 + A4 + A8;
    float emu = __expf(c1 * ((float)(1 << NSQ) / 3.0f));
    float mu = c1 * (1.0f / 3.0f);
    A0 -= mu; A4 -= mu; A8 -= mu;

    float tt = fmaf(A2, A6, A1 * A3);
    tt = fmaf(A5, A7, tt);
    float ss = fmaf(A4, A4, A0 * A0);
    ss = fmaf(A8, A8, ss);
    float nc2 = fmaf(ss, 0.5f, tt);

    float m0  = fmaf(A4, A8, -(A5 * A7));
    float m1n = fmaf(A5, A6, -(A3 * A8));
    float m2  = fmaf(A3, A7, -(A4 * A6));
    float c3  = fmaf(A0, m0, fmaf(A1, m1n, A2 * m2));

    float w0 = fmaf(A0, v0, fmaf(A1, v1, A2 * v2));
    float w1 = fmaf(A3, v0, fmaf(A4, v1, A5 * v2));
    float w2 = fmaf(A6, v0, fmaf(A7, v1, A8 * v2));
    float u0 = fmaf(A0, w0, fmaf(A1, w1, A2 * w2));
    float u1 = fmaf(A3, w0, fmaf(A4, w1, A5 * w2));
    float u2 = fmaf(A6, w0, fmaf(A7, w1, A8 * w2));

    const float invfact[NORD + 1] = {
        1.f, 1.f, 0.5f, 1.f/6.f, 1.f/24.f, 1.f/120.f, 1.f/720.f,
        1.f/5040.f, 1.f/40320.f, 1.f/362880.f, 1.f/3628800.f
    };
    float sa = invfact[NORD], sb = 0.0f, sc = 0.0f;
    #pragma unroll
    for (int k = NORD - 1; k >= 0; k--) {
        float oc = sc;
        float na = fmaf(c3,  oc, invfact[k]);
        float nb = fmaf(nc2, oc, sa);
        sc = sb;
        sa = na;
        sb = nb;
    }

    #pragma unroll
    for (int sq = 0; sq < NSQ; sq++) {
        float bc2 = 2.0f * (sb * sc);
        float cc  = sc * sc;
        float ab2 = 2.0f * (sa * sb);
        float ac2 = 2.0f * (sa * sc);
        float na  = fmaf(bc2, c3, sa * sa);
        float nb  = fmaf(cc, c3, fmaf(bc2, nc2, ab2));
        float ncc = fmaf(cc, nc2, fmaf(sb, sb, ac2));
        sa = na; sb = nb; sc = ncc;
    }

    sa *= emu; sb *= emu; sc *= emu;
    y0 = fmaf(sa, v0, fmaf(sb, w0, sc * u0));
    y1 = fmaf(sa, v1, fmaf(sb, w1, sc * u1));
    y2 = fmaf(sa, v2, fmaf(sb, w2, sc * u2));
}

__global__ __launch_bounds__(256, 3) void expmsc4_kernel(
    const float* __restrict__ x,
    const float* __restrict__ c,
    const float* __restrict__ psi,
    float* __restrict__ out,
    int B)
{
    // psi pre-scaled by 1/2^NSQ; rows padded to 12 floats
    __shared__ __align__(16) float s_psi[72];
    if (threadIdx.x < 72) {
        int row = threadIdx.x / 12, col = threadIdx.x % 12;
        s_psi[threadIdx.x] =
            (col < 9) ? psi[row * 9 + col] * (1.0f / (float)(1 << NSQ)) : 0.0f;
    }
    __syncthreads();

    int t  = blockIdx.x * blockDim.x + threadIdx.x;
    int b0 = 4 * t;
    if (b0 >= B) return;

    if (b0 + 3 < B) {
        // ---- main path: 4 batches, fully aligned vector loads ----
        float cf[24];
        {
            const float4* cq = (const float4*)(c + b0 * 6);
            #pragma unroll
            for (int i = 0; i < 6; i++) {
                float4 q = __ldg(&cq[i]);
                cf[4 * i + 0] = q.x; cf[4 * i + 1] = q.y;
                cf[4 * i + 2] = q.z; cf[4 * i + 3] = q.w;
            }
        }
        float xf[12];
        {
            const float4* xq = (const float4*)(x + b0 * 3);
            #pragma unroll
            for (int i = 0; i < 3; i++) {
                float4 q = __ldg(&xq[i]);
                xf[4 * i + 0] = q.x; xf[4 * i + 1] = q.y;
                xf[4 * i + 2] = q.z; xf[4 * i + 3] = q.w;
            }
        }

        // ---- build 4 A matrices sharing psi-row loads ----
        float A[4][9];
        {
            const float4* pr = (const float4*)s_psi;
            #pragma unroll
            for (int m = 0; m < 6; m++) {
                float4 p0 = pr[m * 3 + 0];
                float4 p1 = pr[m * 3 + 1];
                float  p8 = s_psi[m * 12 + 8];
                float pv[9] = {p0.x, p0.y, p0.z, p0.w, p1.x, p1.y, p1.z, p1.w, p8};
                #pragma unroll
                for (int j = 0; j < 4; j++) {
                    float cm = cf[j * 6 + m];
                    #pragma unroll
                    for (int e = 0; e < 9; e++) {
                        if (m == 0) A[j][e] = cm * pv[e];
                        else        A[j][e] = fmaf(cm, pv[e], A[j][e]);
                    }
                }
            }
        }

        // ---- 4 independent scalar pipelines ----
        float y[12];
        #pragma unroll
        for (int j = 0; j < 4; j++) {
            expm_core_s(A[j][0], A[j][1], A[j][2], A[j][3], A[j][4],
                        A[j][5], A[j][6], A[j][7], A[j][8],
                        xf[j * 3 + 0], xf[j * 3 + 1], xf[j * 3 + 2],
                        y[j * 3 + 0], y[j * 3 + 1], y[j * 3 + 2]);
        }

        // ---- store: 3 aligned float4 ----
        float4* oq = (float4*)(out + b0 * 3);
        oq[0] = make_float4(y[0], y[1], y[2],  y[3]);
        oq[1] = make_float4(y[4], y[5], y[6],  y[7]);
        oq[2] = make_float4(y[8], y[9], y[10], y[11]);
    } else {
        // ---- tail: per-batch scalar path ----
        for (int b = b0; b < B; b++) {
            const float* cp = c + b * 6;
            float cm[6];
            #pragma unroll
            for (int m = 0; m < 6; m++) cm[m] = __ldg(&cp[m]);
            float A[9];
            {
                const float4* pr = (const float4*)s_psi;
                #pragma unroll
                for (int m = 0; m < 6; m++) {
                    float4 p0 = pr[m * 3 + 0];
                    float4 p1 = pr[m * 3 + 1];
                    float  p8 = s_psi[m * 12 + 8];
                    float pv[9] = {p0.x, p0.y, p0.z, p0.w, p1.x, p1.y, p1.z, p1.w, p8};
                    #pragma unroll
                    for (int e = 0; e < 9; e++) {
                        if (m == 0) A[e] = cm[0] * pv[e];
                        else        A[e] = fmaf(cm[m], pv[e], A[e]);
                    }
                }
            }
            const float* xb = x + b * 3;
            float v0 = __ldg(&xb[0]), v1 = __ldg(&xb[1]), v2 = __ldg(&xb[2]);
            float y0, y1, y2;
            expm_core_s(A[0], A[1], A[2], A[3], A[4], A[5], A[6], A[7], A[8],
                        v0, v1, v2, y0, y1, y2);
            float* ob = out + b * 3;
            ob[0] = y0; ob[1] = y1; ob[2] = y2;
        }
    }
}

extern "C" void kernel_launch(void* const* d_in, const int* in_sizes, int n_in,
                              void* d_out, int out_size) {
    const float* x   = (const float*)d_in[0];  // [B,3,1]
    const float* c   = (const float*)d_in[1];  // [B,6]
    const float* psi = (const float*)d_in[2];  // [6,3,3]
    float* out = (float*)d_out;                // [B,3]

    int B = in_sizes[0] / 3;
    int quads = (B + 3) / 4;
    int threads = 256;
    int blocks = (quads + threads - 1) / threads;
    expmsc4_kernel<<<blocks, threads>>>(x, c, psi, out, B);
}